// round 1
// baseline (speedup 1.0000x reference)
#include <cuda_runtime.h>
#include <math.h>

// Problem constants
#define Bb   2
#define Tt   2048
#define Cc   2048
#define NH   16
#define NKV  4
#define HD   128
#define GROUPQ (NH / NKV)

// Scratch buffers (device globals: allocation-free per harness rules)
__device__ float g_Q[(size_t)Bb * Tt * Cc];          // [B*T, C]   (= [b,t,h,d])
__device__ float g_K[(size_t)Bb * Tt * NKV * HD];    // [B*T, 512] (= [b,t,kv,d])
__device__ float g_V[(size_t)Bb * Tt * NKV * HD];
__device__ float g_Y[(size_t)Bb * Tt * Cc];          // attention output, [b,t,h,d]

// ---------------------------------------------------------------------------
// SGEMM: C[M,N] = A[M,K] @ B[K,N], all row-major fp32.
// 128x128 block tile, K-tile 8, 256 threads, 8x8 register tile per thread.
// M,N,K multiples of 128/128/8 (true for all our shapes).
// ---------------------------------------------------------------------------
__global__ __launch_bounds__(256) void sgemm128(const float* __restrict__ A,
                                                const float* __restrict__ Bm,
                                                float* __restrict__ C,
                                                int M, int N, int K)
{
    __shared__ float As[8][132];   // transposed: As[k][m], padded (132) -> conflict-free stores
    __shared__ float Bs[8][128];   // Bs[k][n]

    const int tid = threadIdx.x;
    const int m0 = blockIdx.y * 128;
    const int n0 = blockIdx.x * 128;

    // Global staging assignments
    const int arow = tid >> 1;          // 0..127
    const int acol = (tid & 1) * 4;     // 0 or 4
    const int brow = tid >> 5;          // 0..7
    const int bcol = (tid & 31) * 4;    // 0..124

    const float* Ap = A + (size_t)(m0 + arow) * K + acol;
    const float* Bp = Bm + (size_t)brow * N + n0 + bcol;

    float4 ar = *(const float4*)Ap;
    float4 br = *(const float4*)Bp;

    float acc[8][8];
#pragma unroll
    for (int i = 0; i < 8; i++)
#pragma unroll
        for (int j = 0; j < 8; j++) acc[i][j] = 0.0f;

    const int ty = tid >> 4;   // 0..15 -> rows ty*8..ty*8+7
    const int tx = tid & 15;   // 0..15 -> cols tx*8..tx*8+7

    for (int k0 = 0; k0 < K; k0 += 8) {
        // store staged tile
        As[acol + 0][arow] = ar.x;
        As[acol + 1][arow] = ar.y;
        As[acol + 2][arow] = ar.z;
        As[acol + 3][arow] = ar.w;
        *(float4*)&Bs[brow][bcol] = br;
        __syncthreads();

        if (k0 + 8 < K) {
            ar = *(const float4*)(Ap + (k0 + 8));
            br = *(const float4*)(Bp + (size_t)(k0 + 8) * N);
        }

#pragma unroll
        for (int k = 0; k < 8; k++) {
            float a[8], bf[8];
            *(float4*)(a)     = *(float4*)&As[k][ty * 8];
            *(float4*)(a + 4) = *(float4*)&As[k][ty * 8 + 4];
            *(float4*)(bf)     = *(float4*)&Bs[k][tx * 8];
            *(float4*)(bf + 4) = *(float4*)&Bs[k][tx * 8 + 4];
#pragma unroll
            for (int i = 0; i < 8; i++)
#pragma unroll
                for (int j = 0; j < 8; j++)
                    acc[i][j] = fmaf(a[i], bf[j], acc[i][j]);
        }
        __syncthreads();
    }

#pragma unroll
    for (int i = 0; i < 8; i++) {
        const size_t row = (size_t)(m0 + ty * 8 + i);
        float4 r0 = make_float4(acc[i][0], acc[i][1], acc[i][2], acc[i][3]);
        float4 r1 = make_float4(acc[i][4], acc[i][5], acc[i][6], acc[i][7]);
        *(float4*)&C[row * N + n0 + tx * 8]     = r0;
        *(float4*)&C[row * N + n0 + tx * 8 + 4] = r1;
    }
}

// ---------------------------------------------------------------------------
// Flash attention (causal, GQA). One block handles 128 query rows of one
// (b, h). Iterates over 64-row K/V tiles up to the diagonal with online
// softmax. 256 threads: thread (ty,tx) with ty=tid/16, tx=tid%16 owns
// S rows ty*8..+7 x cols tx*4..+3 and O rows ty*8..+7 x cols tx*8..+7.
// ---------------------------------------------------------------------------
#define AT_BM 128
#define AT_BN 64
#define SOFTMAX_SCALE 0.08838834764831845f  // 1/sqrt(128)
#define NEG_BIG (-3.0e38f)

// Shared memory carve (floats):
//   Qs: 128*132, Ks: 64*132, Vs: 64*128, Ps: 128*68
#define QS_STRIDE 132
#define KS_STRIDE 132
#define VS_STRIDE 128
#define PS_STRIDE 68
#define SMEM_ATTN_FLOATS (AT_BM * QS_STRIDE + AT_BN * KS_STRIDE + AT_BN * VS_STRIDE + AT_BM * PS_STRIDE)
#define SMEM_ATTN_BYTES (SMEM_ATTN_FLOATS * 4)

__global__ __launch_bounds__(256) void attn_kernel()
{
    extern __shared__ float sm[];
    float* Qs = sm;                          // [128][132]
    float* Ks = Qs + AT_BM * QS_STRIDE;      // [64][132]
    float* Vs = Ks + AT_BN * KS_STRIDE;      // [64][128]
    float* Ps = Vs + AT_BN * VS_STRIDE;      // [128][68]

    const int tid = threadIdx.x;
    const int ty = tid >> 4;   // 0..15
    const int tx = tid & 15;   // 0..15

    const int b = blockIdx.z;
    const int h = blockIdx.y;
    const int m0 = gridDim.x - 1 - blockIdx.x;   // biggest tiles first (load balance)
    const int t0 = m0 * AT_BM;
    const int kv = h >> 2;                       // h / GROUPQ

    // Load Q tile [128][128] into smem
    const float* Qg = g_Q + ((size_t)(b * Tt + t0)) * Cc + h * HD;
    for (int s = tid; s < AT_BM * 32; s += 256) {
        int r = s >> 5, c4 = (s & 31) << 2;
        *(float4*)&Qs[r * QS_STRIDE + c4] = *(const float4*)&Qg[(size_t)r * Cc + c4];
    }

    float mrun[8], lrun[8], o[8][8];
#pragma unroll
    for (int i = 0; i < 8; i++) {
        mrun[i] = NEG_BIG;
        lrun[i] = 0.0f;
#pragma unroll
        for (int c = 0; c < 8; c++) o[i][c] = 0.0f;
    }

    const int nkt = 2 * m0 + 2;  // number of 64-wide K tiles needed (causal)
    const float* Kg = g_K + ((size_t)(b * Tt)) * (NKV * HD) + kv * HD;
    const float* Vg = g_V + ((size_t)(b * Tt)) * (NKV * HD) + kv * HD;

    for (int kt = 0; kt < nkt; kt++) {
        const int j0 = kt * AT_BN;

        // Load K/V tiles [64][128]
        for (int s = tid; s < AT_BN * 32; s += 256) {
            int r = s >> 5, c4 = (s & 31) << 2;
            *(float4*)&Ks[r * KS_STRIDE + c4] =
                *(const float4*)&Kg[(size_t)(j0 + r) * (NKV * HD) + c4];
            *(float4*)&Vs[r * VS_STRIDE + c4] =
                *(const float4*)&Vg[(size_t)(j0 + r) * (NKV * HD) + c4];
        }
        __syncthreads();

        // S = Q K^T for this block's 8x4 sub-tile
        float sacc[8][4];
#pragma unroll
        for (int i = 0; i < 8; i++)
#pragma unroll
            for (int j = 0; j < 4; j++) sacc[i][j] = 0.0f;

        for (int k = 0; k < HD; k += 4) {
            float4 kf0 = *(float4*)&Ks[(tx * 4 + 0) * KS_STRIDE + k];
            float4 kf1 = *(float4*)&Ks[(tx * 4 + 1) * KS_STRIDE + k];
            float4 kf2 = *(float4*)&Ks[(tx * 4 + 2) * KS_STRIDE + k];
            float4 kf3 = *(float4*)&Ks[(tx * 4 + 3) * KS_STRIDE + k];
#pragma unroll
            for (int ii = 0; ii < 8; ii++) {
                float4 qf = *(float4*)&Qs[(ty * 8 + ii) * QS_STRIDE + k];
                sacc[ii][0] = fmaf(qf.x, kf0.x, fmaf(qf.y, kf0.y, fmaf(qf.z, kf0.z, fmaf(qf.w, kf0.w, sacc[ii][0]))));
                sacc[ii][1] = fmaf(qf.x, kf1.x, fmaf(qf.y, kf1.y, fmaf(qf.z, kf1.z, fmaf(qf.w, kf1.w, sacc[ii][1]))));
                sacc[ii][2] = fmaf(qf.x, kf2.x, fmaf(qf.y, kf2.y, fmaf(qf.z, kf2.z, fmaf(qf.w, kf2.w, sacc[ii][2]))));
                sacc[ii][3] = fmaf(qf.x, kf3.x, fmaf(qf.y, kf3.y, fmaf(qf.z, kf3.z, fmaf(qf.w, kf3.w, sacc[ii][3]))));
            }
        }

        // scale + causal mask (only the last two tiles touch the diagonal)
        const bool diag = (kt >= nkt - 2);
#pragma unroll
        for (int ii = 0; ii < 8; ii++) {
            const int grow = t0 + ty * 8 + ii;
#pragma unroll
            for (int jj = 0; jj < 4; jj++) {
                sacc[ii][jj] *= SOFTMAX_SCALE;
                if (diag && (j0 + tx * 4 + jj > grow)) sacc[ii][jj] = NEG_BIG;
            }
        }

        // Online softmax per row (reduce across the 16 tx lanes of this row)
#pragma unroll
        for (int ii = 0; ii < 8; ii++) {
            float mx = fmaxf(fmaxf(sacc[ii][0], sacc[ii][1]), fmaxf(sacc[ii][2], sacc[ii][3]));
#pragma unroll
            for (int off = 8; off > 0; off >>= 1)
                mx = fmaxf(mx, __shfl_xor_sync(0xffffffffu, mx, off));
            const float mnew = fmaxf(mrun[ii], mx);
            const float alpha = __expf(mrun[ii] - mnew);
            float rs = 0.0f;
#pragma unroll
            for (int jj = 0; jj < 4; jj++) {
                float p = __expf(sacc[ii][jj] - mnew);
                sacc[ii][jj] = p;
                rs += p;
            }
#pragma unroll
            for (int off = 8; off > 0; off >>= 1)
                rs += __shfl_xor_sync(0xffffffffu, rs, off);
            lrun[ii] = lrun[ii] * alpha + rs;
            mrun[ii] = mnew;
#pragma unroll
            for (int c = 0; c < 8; c++) o[ii][c] *= alpha;
            *(float4*)&Ps[(ty * 8 + ii) * PS_STRIDE + tx * 4] =
                make_float4(sacc[ii][0], sacc[ii][1], sacc[ii][2], sacc[ii][3]);
        }
        __syncthreads();

        // O += P V
        for (int j = 0; j < AT_BN; j += 4) {
            float4 v0a = *(float4*)&Vs[(j + 0) * VS_STRIDE + tx * 8];
            float4 v0b = *(float4*)&Vs[(j + 0) * VS_STRIDE + tx * 8 + 4];
            float4 v1a = *(float4*)&Vs[(j + 1) * VS_STRIDE + tx * 8];
            float4 v1b = *(float4*)&Vs[(j + 1) * VS_STRIDE + tx * 8 + 4];
            float4 v2a = *(float4*)&Vs[(j + 2) * VS_STRIDE + tx * 8];
            float4 v2b = *(float4*)&Vs[(j + 2) * VS_STRIDE + tx * 8 + 4];
            float4 v3a = *(float4*)&Vs[(j + 3) * VS_STRIDE + tx * 8];
            float4 v3b = *(float4*)&Vs[(j + 3) * VS_STRIDE + tx * 8 + 4];
#pragma unroll
            for (int ii = 0; ii < 8; ii++) {
                float4 pf = *(float4*)&Ps[(ty * 8 + ii) * PS_STRIDE + j];
                o[ii][0] = fmaf(pf.x, v0a.x, fmaf(pf.y, v1a.x, fmaf(pf.z, v2a.x, fmaf(pf.w, v3a.x, o[ii][0]))));
                o[ii][1] = fmaf(pf.x, v0a.y, fmaf(pf.y, v1a.y, fmaf(pf.z, v2a.y, fmaf(pf.w, v3a.y, o[ii][1]))));
                o[ii][2] = fmaf(pf.x, v0a.z, fmaf(pf.y, v1a.z, fmaf(pf.z, v2a.z, fmaf(pf.w, v3a.z, o[ii][2]))));
                o[ii][3] = fmaf(pf.x, v0a.w, fmaf(pf.y, v1a.w, fmaf(pf.z, v2a.w, fmaf(pf.w, v3a.w, o[ii][3]))));
                o[ii][4] = fmaf(pf.x, v0b.x, fmaf(pf.y, v1b.x, fmaf(pf.z, v2b.x, fmaf(pf.w, v3b.x, o[ii][4]))));
                o[ii][5] = fmaf(pf.x, v0b.y, fmaf(pf.y, v1b.y, fmaf(pf.z, v2b.y, fmaf(pf.w, v3b.y, o[ii][5]))));
                o[ii][6] = fmaf(pf.x, v0b.z, fmaf(pf.y, v1b.z, fmaf(pf.z, v2b.z, fmaf(pf.w, v3b.z, o[ii][6]))));
                o[ii][7] = fmaf(pf.x, v0b.w, fmaf(pf.y, v1b.w, fmaf(pf.z, v2b.w, fmaf(pf.w, v3b.w, o[ii][7]))));
            }
        }
        __syncthreads();
    }

    // Normalize + write out to g_Y (layout [b,t,h,d])
#pragma unroll
    for (int ii = 0; ii < 8; ii++) {
        const float inv = 1.0f / lrun[ii];
        const size_t row = (size_t)(b * Tt + t0 + ty * 8 + ii);
        float4 r0 = make_float4(o[ii][0] * inv, o[ii][1] * inv, o[ii][2] * inv, o[ii][3] * inv);
        float4 r1 = make_float4(o[ii][4] * inv, o[ii][5] * inv, o[ii][6] * inv, o[ii][7] * inv);
        *(float4*)&g_Y[row * Cc + h * HD + tx * 8]     = r0;
        *(float4*)&g_Y[row * Cc + h * HD + tx * 8 + 4] = r1;
    }
}

// ---------------------------------------------------------------------------
// Launch
// ---------------------------------------------------------------------------
extern "C" void kernel_launch(void* const* d_in, const int* in_sizes, int n_in,
                              void* d_out, int out_size)
{
    const float* x  = (const float*)d_in[0];
    const float* Wq = (const float*)d_in[1];
    const float* Wk = (const float*)d_in[2];
    const float* Wv = (const float*)d_in[3];
    const float* Wo = (const float*)d_in[4];
    float* out = (float*)d_out;

    void *pQ, *pK, *pV, *pY;
    cudaGetSymbolAddress(&pQ, g_Q);
    cudaGetSymbolAddress(&pK, g_K);
    cudaGetSymbolAddress(&pV, g_V);
    cudaGetSymbolAddress(&pY, g_Y);

    const int M = Bb * Tt;           // 4096
    // Projections
    sgemm128<<<dim3(Cc / 128, M / 128), 256>>>(x, Wq, (float*)pQ, M, Cc, Cc);
    sgemm128<<<dim3((NKV * HD) / 128, M / 128), 256>>>(x, Wk, (float*)pK, M, NKV * HD, Cc);
    sgemm128<<<dim3((NKV * HD) / 128, M / 128), 256>>>(x, Wv, (float*)pV, M, NKV * HD, Cc);

    // Attention
    cudaFuncSetAttribute(attn_kernel, cudaFuncAttributeMaxDynamicSharedMemorySize,
                         SMEM_ATTN_BYTES);
    attn_kernel<<<dim3(Tt / AT_BM, NH, Bb), 256, SMEM_ATTN_BYTES>>>();

    // Output projection
    sgemm128<<<dim3(Cc / 128, M / 128), 256>>>((const float*)pY, Wo, out, M, Cc, Cc);
}

// round 2
// speedup vs baseline: 1.6869x; 1.6869x over previous
#include <cuda_runtime.h>
#include <math.h>

// Problem constants
#define Bb   2
#define Tt   2048
#define Cc   2048
#define NH   16
#define NKV  4
#define HD   128
#define GROUPQ (NH / NKV)

// Scratch buffers (device globals: allocation-free per harness rules)
__device__ float g_Q[(size_t)Bb * Tt * Cc];          // [B*T, C]   (= [b,t,h,d])
__device__ float g_K[(size_t)Bb * Tt * NKV * HD];    // [B*T, 512] (= [b,t,kv,d])
__device__ float g_V[(size_t)Bb * Tt * NKV * HD];
__device__ float g_Y[(size_t)Bb * Tt * Cc];          // attention output, [b,t,h,d]

// ---------------------------------------------------------------------------
// TF32 tensor-core GEMM: C[M,N] = A[M,K] @ B[K,N], row-major fp32 in/out.
// mma.sync.aligned.m16n8k8.row.col.f32.tf32.tf32.f32
// Block tile 128x128, K-tile 32, 256 threads = 8 warps (2x4), warp tile 64x32.
// Requires M%128==0, N%128==0, K%32==0 (true for all shapes here).
// ---------------------------------------------------------------------------
#define AS_STRIDE 36    // As[m][k] padded: frag-load bank = lane (conflict-free)
#define BS_STRIDE 136   // Bs[k][n] padded: frag-load bank = 8*(l&3)+(l>>2) (c.f.)

__device__ __forceinline__ unsigned f2tf32(float x) {
    unsigned r;
    asm("cvt.rna.tf32.f32 %0, %1;" : "=r"(r) : "f"(x));
    return r;
}

__device__ __forceinline__ void mma_tf32(float c[4], const unsigned a[4],
                                         const unsigned b[2]) {
    asm volatile(
        "mma.sync.aligned.m16n8k8.row.col.f32.tf32.tf32.f32 "
        "{%0,%1,%2,%3}, {%4,%5,%6,%7}, {%8,%9}, {%0,%1,%2,%3};\n"
        : "+f"(c[0]), "+f"(c[1]), "+f"(c[2]), "+f"(c[3])
        : "r"(a[0]), "r"(a[1]), "r"(a[2]), "r"(a[3]), "r"(b[0]), "r"(b[1]));
}

__global__ __launch_bounds__(256) void tf32gemm(const float* __restrict__ A,
                                                const float* __restrict__ Bm,
                                                float* __restrict__ C,
                                                int M, int N, int K)
{
    __shared__ float As[128 * AS_STRIDE];
    __shared__ float Bs[32 * BS_STRIDE];

    const int tid = threadIdx.x;
    const int lane = tid & 31;
    const int warp = tid >> 5;
    const int warp_m = warp >> 2;   // 0..1 -> rows warp_m*64
    const int warp_n = warp & 3;    // 0..3 -> cols warp_n*32

    const int m0 = blockIdx.y * 128;
    const int n0 = blockIdx.x * 128;

    // staging assignment
    const int ar = tid >> 3;          // 0..31 (row within 32-row pass)
    const int ac = (tid & 7) * 4;     // 0..28
    const int br = tid >> 5;          // 0..7  (row within 8-row pass)
    const int bc = (lane) * 4;        // 0..124

    const float* Ap = A + (size_t)(m0 + ar) * K + ac;
    const float* Bp = Bm + (size_t)br * N + n0 + bc;

    float4 areg[4], breg[4];
#pragma unroll
    for (int p = 0; p < 4; p++) areg[p] = *(const float4*)(Ap + (size_t)(p * 32) * K);
#pragma unroll
    for (int p = 0; p < 4; p++) breg[p] = *(const float4*)(Bp + (size_t)(p * 8) * N);

    float acc[4][4][4];
#pragma unroll
    for (int mt = 0; mt < 4; mt++)
#pragma unroll
        for (int nt = 0; nt < 4; nt++)
#pragma unroll
            for (int r = 0; r < 4; r++) acc[mt][nt][r] = 0.0f;

    const int lq = lane >> 2;   // 0..7
    const int lr = lane & 3;    // 0..3

    for (int k0 = 0; k0 < K; k0 += 32) {
        // stage (convert fp32 -> tf32 bits once, at store time)
#pragma unroll
        for (int p = 0; p < 4; p++) {
            float4 v = areg[p];
            float4 t;
            t.x = __uint_as_float(f2tf32(v.x));
            t.y = __uint_as_float(f2tf32(v.y));
            t.z = __uint_as_float(f2tf32(v.z));
            t.w = __uint_as_float(f2tf32(v.w));
            *(float4*)&As[(p * 32 + ar) * AS_STRIDE + ac] = t;
        }
#pragma unroll
        for (int p = 0; p < 4; p++) {
            float4 v = breg[p];
            float4 t;
            t.x = __uint_as_float(f2tf32(v.x));
            t.y = __uint_as_float(f2tf32(v.y));
            t.z = __uint_as_float(f2tf32(v.z));
            t.w = __uint_as_float(f2tf32(v.w));
            *(float4*)&Bs[(p * 8 + br) * BS_STRIDE + bc] = t;
        }
        __syncthreads();

        if (k0 + 32 < K) {
#pragma unroll
            for (int p = 0; p < 4; p++)
                areg[p] = *(const float4*)(Ap + (size_t)(p * 32) * K + (k0 + 32));
#pragma unroll
            for (int p = 0; p < 4; p++)
                breg[p] = *(const float4*)(Bp + (size_t)(k0 + 32 + p * 8) * N);
        }

#pragma unroll
        for (int kk = 0; kk < 4; kk++) {
            const int kb = kk * 8;
            unsigned afrag[4][4], bfrag[4][2];
#pragma unroll
            for (int mt = 0; mt < 4; mt++) {
                const int mrow = warp_m * 64 + mt * 16 + lq;
                afrag[mt][0] = __float_as_uint(As[mrow * AS_STRIDE + kb + lr]);
                afrag[mt][1] = __float_as_uint(As[(mrow + 8) * AS_STRIDE + kb + lr]);
                afrag[mt][2] = __float_as_uint(As[mrow * AS_STRIDE + kb + lr + 4]);
                afrag[mt][3] = __float_as_uint(As[(mrow + 8) * AS_STRIDE + kb + lr + 4]);
            }
#pragma unroll
            for (int nt = 0; nt < 4; nt++) {
                const int ncol = warp_n * 32 + nt * 8 + lq;
                bfrag[nt][0] = __float_as_uint(Bs[(kb + lr) * BS_STRIDE + ncol]);
                bfrag[nt][1] = __float_as_uint(Bs[(kb + lr + 4) * BS_STRIDE + ncol]);
            }
#pragma unroll
            for (int mt = 0; mt < 4; mt++)
#pragma unroll
                for (int nt = 0; nt < 4; nt++)
                    mma_tf32(acc[mt][nt], afrag[mt], bfrag[nt]);
        }
        __syncthreads();
    }

    // epilogue: c0,c1 at (row, 2*lr), c2,c3 at (row+8, 2*lr)
#pragma unroll
    for (int mt = 0; mt < 4; mt++) {
        const int r0 = m0 + warp_m * 64 + mt * 16 + lq;
#pragma unroll
        for (int nt = 0; nt < 4; nt++) {
            const int col = n0 + warp_n * 32 + nt * 8 + 2 * lr;
            float2 lo = make_float2(acc[mt][nt][0], acc[mt][nt][1]);
            float2 hi = make_float2(acc[mt][nt][2], acc[mt][nt][3]);
            *(float2*)&C[(size_t)r0 * N + col] = lo;
            *(float2*)&C[(size_t)(r0 + 8) * N + col] = hi;
        }
    }
}

// ---------------------------------------------------------------------------
// Flash attention (causal, GQA) — unchanged from the passing R1 kernel.
// ---------------------------------------------------------------------------
#define AT_BM 128
#define AT_BN 64
#define SOFTMAX_SCALE 0.08838834764831845f  // 1/sqrt(128)
#define NEG_BIG (-3.0e38f)

#define QS_STRIDE 132
#define KS_STRIDE 132
#define VS_STRIDE 128
#define PS_STRIDE 68
#define SMEM_ATTN_FLOATS (AT_BM * QS_STRIDE + AT_BN * KS_STRIDE + AT_BN * VS_STRIDE + AT_BM * PS_STRIDE)
#define SMEM_ATTN_BYTES (SMEM_ATTN_FLOATS * 4)

__global__ __launch_bounds__(256) void attn_kernel()
{
    extern __shared__ float sm[];
    float* Qs = sm;                          // [128][132]
    float* Ks = Qs + AT_BM * QS_STRIDE;      // [64][132]
    float* Vs = Ks + AT_BN * KS_STRIDE;      // [64][128]
    float* Ps = Vs + AT_BN * VS_STRIDE;      // [128][68]

    const int tid = threadIdx.x;
    const int ty = tid >> 4;   // 0..15
    const int tx = tid & 15;   // 0..15

    const int b = blockIdx.z;
    const int h = blockIdx.y;
    const int m0 = gridDim.x - 1 - blockIdx.x;   // biggest tiles first
    const int t0 = m0 * AT_BM;
    const int kv = h >> 2;

    const float* Qg = g_Q + ((size_t)(b * Tt + t0)) * Cc + h * HD;
    for (int s = tid; s < AT_BM * 32; s += 256) {
        int r = s >> 5, c4 = (s & 31) << 2;
        *(float4*)&Qs[r * QS_STRIDE + c4] = *(const float4*)&Qg[(size_t)r * Cc + c4];
    }

    float mrun[8], lrun[8], o[8][8];
#pragma unroll
    for (int i = 0; i < 8; i++) {
        mrun[i] = NEG_BIG;
        lrun[i] = 0.0f;
#pragma unroll
        for (int c = 0; c < 8; c++) o[i][c] = 0.0f;
    }

    const int nkt = 2 * m0 + 2;
    const float* Kg = g_K + ((size_t)(b * Tt)) * (NKV * HD) + kv * HD;
    const float* Vg = g_V + ((size_t)(b * Tt)) * (NKV * HD) + kv * HD;

    for (int kt = 0; kt < nkt; kt++) {
        const int j0 = kt * AT_BN;

        for (int s = tid; s < AT_BN * 32; s += 256) {
            int r = s >> 5, c4 = (s & 31) << 2;
            *(float4*)&Ks[r * KS_STRIDE + c4] =
                *(const float4*)&Kg[(size_t)(j0 + r) * (NKV * HD) + c4];
            *(float4*)&Vs[r * VS_STRIDE + c4] =
                *(const float4*)&Vg[(size_t)(j0 + r) * (NKV * HD) + c4];
        }
        __syncthreads();

        float sacc[8][4];
#pragma unroll
        for (int i = 0; i < 8; i++)
#pragma unroll
            for (int j = 0; j < 4; j++) sacc[i][j] = 0.0f;

        for (int k = 0; k < HD; k += 4) {
            float4 kf0 = *(float4*)&Ks[(tx * 4 + 0) * KS_STRIDE + k];
            float4 kf1 = *(float4*)&Ks[(tx * 4 + 1) * KS_STRIDE + k];
            float4 kf2 = *(float4*)&Ks[(tx * 4 + 2) * KS_STRIDE + k];
            float4 kf3 = *(float4*)&Ks[(tx * 4 + 3) * KS_STRIDE + k];
#pragma unroll
            for (int ii = 0; ii < 8; ii++) {
                float4 qf = *(float4*)&Qs[(ty * 8 + ii) * QS_STRIDE + k];
                sacc[ii][0] = fmaf(qf.x, kf0.x, fmaf(qf.y, kf0.y, fmaf(qf.z, kf0.z, fmaf(qf.w, kf0.w, sacc[ii][0]))));
                sacc[ii][1] = fmaf(qf.x, kf1.x, fmaf(qf.y, kf1.y, fmaf(qf.z, kf1.z, fmaf(qf.w, kf1.w, sacc[ii][1]))));
                sacc[ii][2] = fmaf(qf.x, kf2.x, fmaf(qf.y, kf2.y, fmaf(qf.z, kf2.z, fmaf(qf.w, kf2.w, sacc[ii][2]))));
                sacc[ii][3] = fmaf(qf.x, kf3.x, fmaf(qf.y, kf3.y, fmaf(qf.z, kf3.z, fmaf(qf.w, kf3.w, sacc[ii][3]))));
            }
        }

        const bool diag = (kt >= nkt - 2);
#pragma unroll
        for (int ii = 0; ii < 8; ii++) {
            const int grow = t0 + ty * 8 + ii;
#pragma unroll
            for (int jj = 0; jj < 4; jj++) {
                sacc[ii][jj] *= SOFTMAX_SCALE;
                if (diag && (j0 + tx * 4 + jj > grow)) sacc[ii][jj] = NEG_BIG;
            }
        }

#pragma unroll
        for (int ii = 0; ii < 8; ii++) {
            float mx = fmaxf(fmaxf(sacc[ii][0], sacc[ii][1]), fmaxf(sacc[ii][2], sacc[ii][3]));
#pragma unroll
            for (int off = 8; off > 0; off >>= 1)
                mx = fmaxf(mx, __shfl_xor_sync(0xffffffffu, mx, off));
            const float mnew = fmaxf(mrun[ii], mx);
            const float alpha = __expf(mrun[ii] - mnew);
            float rs = 0.0f;
#pragma unroll
            for (int jj = 0; jj < 4; jj++) {
                float p = __expf(sacc[ii][jj] - mnew);
                sacc[ii][jj] = p;
                rs += p;
            }
#pragma unroll
            for (int off = 8; off > 0; off >>= 1)
                rs += __shfl_xor_sync(0xffffffffu, rs, off);
            lrun[ii] = lrun[ii] * alpha + rs;
            mrun[ii] = mnew;
#pragma unroll
            for (int c = 0; c < 8; c++) o[ii][c] *= alpha;
            *(float4*)&Ps[(ty * 8 + ii) * PS_STRIDE + tx * 4] =
                make_float4(sacc[ii][0], sacc[ii][1], sacc[ii][2], sacc[ii][3]);
        }
        __syncthreads();

        for (int j = 0; j < AT_BN; j += 4) {
            float4 v0a = *(float4*)&Vs[(j + 0) * VS_STRIDE + tx * 8];
            float4 v0b = *(float4*)&Vs[(j + 0) * VS_STRIDE + tx * 8 + 4];
            float4 v1a = *(float4*)&Vs[(j + 1) * VS_STRIDE + tx * 8];
            float4 v1b = *(float4*)&Vs[(j + 1) * VS_STRIDE + tx * 8 + 4];
            float4 v2a = *(float4*)&Vs[(j + 2) * VS_STRIDE + tx * 8];
            float4 v2b = *(float4*)&Vs[(j + 2) * VS_STRIDE + tx * 8 + 4];
            float4 v3a = *(float4*)&Vs[(j + 3) * VS_STRIDE + tx * 8];
            float4 v3b = *(float4*)&Vs[(j + 3) * VS_STRIDE + tx * 8 + 4];
#pragma unroll
            for (int ii = 0; ii < 8; ii++) {
                float4 pf = *(float4*)&Ps[(ty * 8 + ii) * PS_STRIDE + j];
                o[ii][0] = fmaf(pf.x, v0a.x, fmaf(pf.y, v1a.x, fmaf(pf.z, v2a.x, fmaf(pf.w, v3a.x, o[ii][0]))));
                o[ii][1] = fmaf(pf.x, v0a.y, fmaf(pf.y, v1a.y, fmaf(pf.z, v2a.y, fmaf(pf.w, v3a.y, o[ii][1]))));
                o[ii][2] = fmaf(pf.x, v0a.z, fmaf(pf.y, v1a.z, fmaf(pf.z, v2a.z, fmaf(pf.w, v3a.z, o[ii][2]))));
                o[ii][3] = fmaf(pf.x, v0a.w, fmaf(pf.y, v1a.w, fmaf(pf.z, v2a.w, fmaf(pf.w, v3a.w, o[ii][3]))));
                o[ii][4] = fmaf(pf.x, v0b.x, fmaf(pf.y, v1b.x, fmaf(pf.z, v2b.x, fmaf(pf.w, v3b.x, o[ii][4]))));
                o[ii][5] = fmaf(pf.x, v0b.y, fmaf(pf.y, v1b.y, fmaf(pf.z, v2b.y, fmaf(pf.w, v3b.y, o[ii][5]))));
                o[ii][6] = fmaf(pf.x, v0b.z, fmaf(pf.y, v1b.z, fmaf(pf.z, v2b.z, fmaf(pf.w, v3b.z, o[ii][6]))));
                o[ii][7] = fmaf(pf.x, v0b.w, fmaf(pf.y, v1b.w, fmaf(pf.z, v2b.w, fmaf(pf.w, v3b.w, o[ii][7]))));
            }
        }
        __syncthreads();
    }

#pragma unroll
    for (int ii = 0; ii < 8; ii++) {
        const float inv = 1.0f / lrun[ii];
        const size_t row = (size_t)(b * Tt + t0 + ty * 8 + ii);
        float4 r0 = make_float4(o[ii][0] * inv, o[ii][1] * inv, o[ii][2] * inv, o[ii][3] * inv);
        float4 r1 = make_float4(o[ii][4] * inv, o[ii][5] * inv, o[ii][6] * inv, o[ii][7] * inv);
        *(float4*)&g_Y[row * Cc + h * HD + tx * 8]     = r0;
        *(float4*)&g_Y[row * Cc + h * HD + tx * 8 + 4] = r1;
    }
}

// ---------------------------------------------------------------------------
// Launch
// ---------------------------------------------------------------------------
extern "C" void kernel_launch(void* const* d_in, const int* in_sizes, int n_in,
                              void* d_out, int out_size)
{
    const float* x  = (const float*)d_in[0];
    const float* Wq = (const float*)d_in[1];
    const float* Wk = (const float*)d_in[2];
    const float* Wv = (const float*)d_in[3];
    const float* Wo = (const float*)d_in[4];
    float* out = (float*)d_out;

    void *pQ, *pK, *pV, *pY;
    cudaGetSymbolAddress(&pQ, g_Q);
    cudaGetSymbolAddress(&pK, g_K);
    cudaGetSymbolAddress(&pV, g_V);
    cudaGetSymbolAddress(&pY, g_Y);

    const int M = Bb * Tt;           // 4096

    // Projections (tf32 tensor cores)
    tf32gemm<<<dim3(Cc / 128, M / 128), 256>>>(x, Wq, (float*)pQ, M, Cc, Cc);
    tf32gemm<<<dim3((NKV * HD) / 128, M / 128), 256>>>(x, Wk, (float*)pK, M, NKV * HD, Cc);
    tf32gemm<<<dim3((NKV * HD) / 128, M / 128), 256>>>(x, Wv, (float*)pV, M, NKV * HD, Cc);

    // Attention (unchanged fp32 flash kernel)
    cudaFuncSetAttribute(attn_kernel, cudaFuncAttributeMaxDynamicSharedMemorySize,
                         SMEM_ATTN_BYTES);
    attn_kernel<<<dim3(Tt / AT_BM, NH, Bb), 256, SMEM_ATTN_BYTES>>>();

    // Output projection (tf32 tensor cores)
    tf32gemm<<<dim3(Cc / 128, M / 128), 256>>>((const float*)pY, Wo, out, M, Cc, Cc);
}

// round 3
// speedup vs baseline: 3.3539x; 1.9882x over previous
#include <cuda_runtime.h>
#include <cuda_bf16.h>
#include <math.h>

// Problem constants
#define Bb   2
#define Tt   2048
#define Cc   2048
#define NH   16
#define NKV  4
#define HD   128

// Scratch buffers
__device__ float g_Q[(size_t)Bb * Tt * Cc];
__device__ float g_K[(size_t)Bb * Tt * NKV * HD];
__device__ float g_V[(size_t)Bb * Tt * NKV * HD];
__device__ float g_Y[(size_t)Bb * Tt * Cc];

// ---------------------------------------------------------------------------
// TF32 tensor-core GEMM (unchanged from passing R2 kernel)
// ---------------------------------------------------------------------------
#define AS_STRIDE 36
#define BS_STRIDE 136

__device__ __forceinline__ unsigned f2tf32(float x) {
    unsigned r;
    asm("cvt.rna.tf32.f32 %0, %1;" : "=r"(r) : "f"(x));
    return r;
}

__device__ __forceinline__ void mma_tf32(float c[4], const unsigned a[4],
                                         const unsigned b[2]) {
    asm volatile(
        "mma.sync.aligned.m16n8k8.row.col.f32.tf32.tf32.f32 "
        "{%0,%1,%2,%3}, {%4,%5,%6,%7}, {%8,%9}, {%0,%1,%2,%3};\n"
        : "+f"(c[0]), "+f"(c[1]), "+f"(c[2]), "+f"(c[3])
        : "r"(a[0]), "r"(a[1]), "r"(a[2]), "r"(a[3]), "r"(b[0]), "r"(b[1]));
}

__global__ __launch_bounds__(256) void tf32gemm(const float* __restrict__ A,
                                                const float* __restrict__ Bm,
                                                float* __restrict__ C,
                                                int M, int N, int K)
{
    __shared__ float As[128 * AS_STRIDE];
    __shared__ float Bs[32 * BS_STRIDE];

    const int tid = threadIdx.x;
    const int lane = tid & 31;
    const int warp = tid >> 5;
    const int warp_m = warp >> 2;
    const int warp_n = warp & 3;

    const int m0 = blockIdx.y * 128;
    const int n0 = blockIdx.x * 128;

    const int ar = tid >> 3;
    const int ac = (tid & 7) * 4;
    const int br = tid >> 5;
    const int bc = lane * 4;

    const float* Ap = A + (size_t)(m0 + ar) * K + ac;
    const float* Bp = Bm + (size_t)br * N + n0 + bc;

    float4 areg[4], breg[4];
#pragma unroll
    for (int p = 0; p < 4; p++) areg[p] = *(const float4*)(Ap + (size_t)(p * 32) * K);
#pragma unroll
    for (int p = 0; p < 4; p++) breg[p] = *(const float4*)(Bp + (size_t)(p * 8) * N);

    float acc[4][4][4];
#pragma unroll
    for (int mt = 0; mt < 4; mt++)
#pragma unroll
        for (int nt = 0; nt < 4; nt++)
#pragma unroll
            for (int r = 0; r < 4; r++) acc[mt][nt][r] = 0.0f;

    const int lq = lane >> 2;
    const int lr = lane & 3;

    for (int k0 = 0; k0 < K; k0 += 32) {
#pragma unroll
        for (int p = 0; p < 4; p++) {
            float4 v = areg[p];
            float4 t;
            t.x = __uint_as_float(f2tf32(v.x));
            t.y = __uint_as_float(f2tf32(v.y));
            t.z = __uint_as_float(f2tf32(v.z));
            t.w = __uint_as_float(f2tf32(v.w));
            *(float4*)&As[(p * 32 + ar) * AS_STRIDE + ac] = t;
        }
#pragma unroll
        for (int p = 0; p < 4; p++) {
            float4 v = breg[p];
            float4 t;
            t.x = __uint_as_float(f2tf32(v.x));
            t.y = __uint_as_float(f2tf32(v.y));
            t.z = __uint_as_float(f2tf32(v.z));
            t.w = __uint_as_float(f2tf32(v.w));
            *(float4*)&Bs[(p * 8 + br) * BS_STRIDE + bc] = t;
        }
        __syncthreads();

        if (k0 + 32 < K) {
#pragma unroll
            for (int p = 0; p < 4; p++)
                areg[p] = *(const float4*)(Ap + (size_t)(p * 32) * K + (k0 + 32));
#pragma unroll
            for (int p = 0; p < 4; p++)
                breg[p] = *(const float4*)(Bp + (size_t)(k0 + 32 + p * 8) * N);
        }

#pragma unroll
        for (int kk = 0; kk < 4; kk++) {
            const int kb = kk * 8;
            unsigned afrag[4][4], bfrag[4][2];
#pragma unroll
            for (int mt = 0; mt < 4; mt++) {
                const int mrow = warp_m * 64 + mt * 16 + lq;
                afrag[mt][0] = __float_as_uint(As[mrow * AS_STRIDE + kb + lr]);
                afrag[mt][1] = __float_as_uint(As[(mrow + 8) * AS_STRIDE + kb + lr]);
                afrag[mt][2] = __float_as_uint(As[mrow * AS_STRIDE + kb + lr + 4]);
                afrag[mt][3] = __float_as_uint(As[(mrow + 8) * AS_STRIDE + kb + lr + 4]);
            }
#pragma unroll
            for (int nt = 0; nt < 4; nt++) {
                const int ncol = warp_n * 32 + nt * 8 + lq;
                bfrag[nt][0] = __float_as_uint(Bs[(kb + lr) * BS_STRIDE + ncol]);
                bfrag[nt][1] = __float_as_uint(Bs[(kb + lr + 4) * BS_STRIDE + ncol]);
            }
#pragma unroll
            for (int mt = 0; mt < 4; mt++)
#pragma unroll
                for (int nt = 0; nt < 4; nt++)
                    mma_tf32(acc[mt][nt], afrag[mt], bfrag[nt]);
        }
        __syncthreads();
    }

#pragma unroll
    for (int mt = 0; mt < 4; mt++) {
        const int r0 = m0 + warp_m * 64 + mt * 16 + lq;
#pragma unroll
        for (int nt = 0; nt < 4; nt++) {
            const int col = n0 + warp_n * 32 + nt * 8 + 2 * lr;
            *(float2*)&C[(size_t)r0 * N + col] = make_float2(acc[mt][nt][0], acc[mt][nt][1]);
            *(float2*)&C[(size_t)(r0 + 8) * N + col] = make_float2(acc[mt][nt][2], acc[mt][nt][3]);
        }
    }
}

// ---------------------------------------------------------------------------
// Tensor-core flash attention (causal, GQA), bf16 3-term-split MMA (~fp32 acc).
// BM=128, BN=64, 8 warps x 16 rows. S accum registers feed P*V directly.
// ---------------------------------------------------------------------------
#define SOFTMAX_SCALE 0.08838834764831845f
#define NEG_BIG (-3.0e38f)
#define TS 136   // b16 row stride for all attention smem tiles

// smem byte offsets
#define QH_B 0
#define QL_B 34816
#define KH_B 69632
#define KL_B 87040
#define VH_B 104448
#define VL_B 121856
#define ATTN_SMEM_BYTES 139264

__device__ __forceinline__ void ldsm4(unsigned* r, unsigned addr) {
    asm volatile("ldmatrix.sync.aligned.m8n8.x4.shared.b16 {%0,%1,%2,%3}, [%4];\n"
                 : "=r"(r[0]), "=r"(r[1]), "=r"(r[2]), "=r"(r[3]) : "r"(addr));
}
__device__ __forceinline__ void ldsm4t(unsigned* r, unsigned addr) {
    asm volatile("ldmatrix.sync.aligned.m8n8.x4.trans.shared.b16 {%0,%1,%2,%3}, [%4];\n"
                 : "=r"(r[0]), "=r"(r[1]), "=r"(r[2]), "=r"(r[3]) : "r"(addr));
}
__device__ __forceinline__ void mma_bf16(float* c, const unsigned* a,
                                         unsigned b0, unsigned b1) {
    asm volatile(
        "mma.sync.aligned.m16n8k16.row.col.f32.bf16.bf16.f32 "
        "{%0,%1,%2,%3}, {%4,%5,%6,%7}, {%8,%9}, {%0,%1,%2,%3};\n"
        : "+f"(c[0]), "+f"(c[1]), "+f"(c[2]), "+f"(c[3])
        : "r"(a[0]), "r"(a[1]), "r"(a[2]), "r"(a[3]), "r"(b0), "r"(b1));
}

__device__ __forceinline__ void split4(float4 v, uint2& hw, uint2& lw) {
    float f[4] = {v.x, v.y, v.z, v.w};
    unsigned hh[4], ll[4];
#pragma unroll
    for (int i = 0; i < 4; i++) {
        __nv_bfloat16 bh = __float2bfloat16_rn(f[i]);
        float fh = __bfloat162float(bh);
        __nv_bfloat16 bl = __float2bfloat16_rn(f[i] - fh);
        hh[i] = __bfloat16_as_ushort(bh);
        ll[i] = __bfloat16_as_ushort(bl);
    }
    hw.x = hh[0] | (hh[1] << 16);
    hw.y = hh[2] | (hh[3] << 16);
    lw.x = ll[0] | (ll[1] << 16);
    lw.y = ll[2] | (ll[3] << 16);
}

__device__ __forceinline__ void split2(float a, float b, unsigned& hi, unsigned& lo) {
    __nv_bfloat16 ah = __float2bfloat16_rn(a);
    __nv_bfloat16 bh = __float2bfloat16_rn(b);
    float af = __bfloat162float(ah), bf = __bfloat162float(bh);
    __nv_bfloat16 al = __float2bfloat16_rn(a - af);
    __nv_bfloat16 bl = __float2bfloat16_rn(b - bf);
    hi = (unsigned)__bfloat16_as_ushort(ah) | ((unsigned)__bfloat16_as_ushort(bh) << 16);
    lo = (unsigned)__bfloat16_as_ushort(al) | ((unsigned)__bfloat16_as_ushort(bl) << 16);
}

__global__ __launch_bounds__(256) void attn_mma()
{
    extern __shared__ unsigned short smb[];
    unsigned short* Qh = smb;
    unsigned short* Ql = smb + 17408;
    unsigned short* Kh = smb + 34816;
    unsigned short* Kl = smb + 43520;
    unsigned short* Vh = smb + 52224;
    unsigned short* Vl = smb + 60928;

    const int tid  = threadIdx.x;
    const int lane = tid & 31;
    const int w    = tid >> 5;

    const int b  = blockIdx.z;
    const int h  = blockIdx.y;
    const int m0 = gridDim.x - 1 - blockIdx.x;   // longest-first
    const int t0 = m0 * 128;
    const int kv = h >> 2;

    const unsigned sbase = (unsigned)__cvta_generic_to_shared(smb);

    // ---- stage Q tile (128 x 128), split bf16 hi/lo ----
    const float* Qg = g_Q + (size_t)(b * Tt + t0) * Cc + h * HD;
#pragma unroll
    for (int p = 0; p < 16; p++) {
        int idx = tid + p * 256;
        int r = idx >> 5;
        int c4 = (idx & 31) << 2;
        float4 v = *(const float4*)&Qg[(size_t)r * Cc + c4];
        uint2 hw, lw;
        split4(v, hw, lw);
        *(uint2*)&Qh[r * TS + c4] = hw;
        *(uint2*)&Ql[r * TS + c4] = lw;
    }

    float oacc[16][4];
#pragma unroll
    for (int i = 0; i < 16; i++)
#pragma unroll
        for (int e = 0; e < 4; e++) oacc[i][e] = 0.0f;
    float mrun0 = NEG_BIG, mrun1 = NEG_BIG, lrun0 = 0.0f, lrun1 = 0.0f;

    const int nkt = 2 * m0 + 2;
    const float* Kg = g_K + (size_t)(b * Tt) * (NKV * HD) + kv * HD;
    const float* Vg = g_V + (size_t)(b * Tt) * (NKV * HD) + kv * HD;

    // per-thread ldmatrix address components
    const int lt = lane >> 3;         // tile index 0..3
    const int l7 = lane & 7;

    for (int kt = 0; kt < nkt; kt++) {
        const int j0 = kt * 64;
        __syncthreads();   // previous tile's reads done before restage

        // ---- stage K/V tiles (64 x 128) split bf16 hi/lo ----
#pragma unroll
        for (int p = 0; p < 8; p++) {
            int idx = tid + p * 256;
            int r = idx >> 5;
            int c4 = (idx & 31) << 2;
            float4 kvv = *(const float4*)&Kg[(size_t)(j0 + r) * (NKV * HD) + c4];
            uint2 hw, lw;
            split4(kvv, hw, lw);
            *(uint2*)&Kh[r * TS + c4] = hw;
            *(uint2*)&Kl[r * TS + c4] = lw;
            float4 vv = *(const float4*)&Vg[(size_t)(j0 + r) * (NKV * HD) + c4];
            split4(vv, hw, lw);
            *(uint2*)&Vh[r * TS + c4] = hw;
            *(uint2*)&Vl[r * TS + c4] = lw;
        }
        __syncthreads();

        // ---- S = Q K^T (bf16 x3 split, fp32 accum) ----
        float sacc[8][4];
#pragma unroll
        for (int i = 0; i < 8; i++)
#pragma unroll
            for (int e = 0; e < 4; e++) sacc[i][e] = 0.0f;

#pragma unroll
        for (int kk = 0; kk < 8; kk++) {
            const int k0 = kk * 16;
            unsigned ah[4], al[4];
            {
                int row = w * 16 + ((lt & 1) << 3) + l7;
                int col = k0 + ((lt >> 1) << 3);
                unsigned addr = sbase + QH_B + (unsigned)(row * TS + col) * 2;
                ldsm4(ah, addr);
                ldsm4(al, addr + (QL_B - QH_B));
            }
#pragma unroll
            for (int g = 0; g < 4; g++) {
                unsigned bh[4], bl[4];
                int row = g * 16 + (((lt >> 1) & 1) << 3) + l7;
                int col = k0 + ((lt & 1) << 3);
                unsigned addr = sbase + KH_B + (unsigned)(row * TS + col) * 2;
                ldsm4(bh, addr);
                ldsm4(bl, addr + (KL_B - KH_B));
                mma_bf16(sacc[2 * g],     ah, bh[0], bh[1]);
                mma_bf16(sacc[2 * g],     ah, bl[0], bl[1]);
                mma_bf16(sacc[2 * g],     al, bh[0], bh[1]);
                mma_bf16(sacc[2 * g + 1], ah, bh[2], bh[3]);
                mma_bf16(sacc[2 * g + 1], ah, bl[2], bl[3]);
                mma_bf16(sacc[2 * g + 1], al, bh[2], bh[3]);
            }
        }

        // ---- scale + causal mask + online softmax ----
        const bool diag = (kt >= nkt - 2);
        float mx0 = NEG_BIG, mx1 = NEG_BIG;
        const int rbase = t0 + w * 16 + (lane >> 2);
        const int cbase = j0 + 2 * (lane & 3);
#pragma unroll
        for (int nt = 0; nt < 8; nt++) {
#pragma unroll
            for (int e = 0; e < 4; e++) {
                float s = sacc[nt][e] * SOFTMAX_SCALE;
                if (diag) {
                    int col = cbase + nt * 8 + (e & 1);
                    int row = rbase + ((e & 2) << 2);
                    if (col > row) s = NEG_BIG;
                }
                sacc[nt][e] = s;
                if (e < 2) mx0 = fmaxf(mx0, s);
                else       mx1 = fmaxf(mx1, s);
            }
        }
        mx0 = fmaxf(mx0, __shfl_xor_sync(0xffffffffu, mx0, 1));
        mx0 = fmaxf(mx0, __shfl_xor_sync(0xffffffffu, mx0, 2));
        mx1 = fmaxf(mx1, __shfl_xor_sync(0xffffffffu, mx1, 1));
        mx1 = fmaxf(mx1, __shfl_xor_sync(0xffffffffu, mx1, 2));

        const float mn0 = fmaxf(mrun0, mx0);
        const float mn1 = fmaxf(mrun1, mx1);
        const float al0 = __expf(mrun0 - mn0);
        const float al1 = __expf(mrun1 - mn1);
        float rs0 = 0.0f, rs1 = 0.0f;
#pragma unroll
        for (int nt = 0; nt < 8; nt++) {
#pragma unroll
            for (int e = 0; e < 4; e++) {
                float p = __expf(sacc[nt][e] - (e < 2 ? mn0 : mn1));
                sacc[nt][e] = p;
                if (e < 2) rs0 += p;
                else       rs1 += p;
            }
        }
        rs0 += __shfl_xor_sync(0xffffffffu, rs0, 1);
        rs0 += __shfl_xor_sync(0xffffffffu, rs0, 2);
        rs1 += __shfl_xor_sync(0xffffffffu, rs1, 1);
        rs1 += __shfl_xor_sync(0xffffffffu, rs1, 2);
        lrun0 = lrun0 * al0 + rs0;
        lrun1 = lrun1 * al1 + rs1;
        mrun0 = mn0;
        mrun1 = mn1;
#pragma unroll
        for (int i = 0; i < 16; i++) {
            oacc[i][0] *= al0;
            oacc[i][1] *= al0;
            oacc[i][2] *= al1;
            oacc[i][3] *= al1;
        }

        // ---- O += P V (bf16 x3 split) ----
#pragma unroll
        for (int kk = 0; kk < 4; kk++) {
            unsigned aph[4], apl[4];
            split2(sacc[2 * kk][0],     sacc[2 * kk][1],     aph[0], apl[0]);
            split2(sacc[2 * kk][2],     sacc[2 * kk][3],     aph[1], apl[1]);
            split2(sacc[2 * kk + 1][0], sacc[2 * kk + 1][1], aph[2], apl[2]);
            split2(sacc[2 * kk + 1][2], sacc[2 * kk + 1][3], aph[3], apl[3]);
#pragma unroll
            for (int g = 0; g < 8; g++) {
                unsigned bh[4], bl[4];
                int row = kk * 16 + ((lt & 1) << 3) + l7;   // seq (k)
                int col = g * 16 + (((lt >> 1) & 1) << 3);  // headdim (n)
                unsigned addr = sbase + VH_B + (unsigned)(row * TS + col) * 2;
                ldsm4t(bh, addr);
                ldsm4t(bl, addr + (VL_B - VH_B));
                mma_bf16(oacc[2 * g],     aph, bh[0], bh[1]);
                mma_bf16(oacc[2 * g],     aph, bl[0], bl[1]);
                mma_bf16(oacc[2 * g],     apl, bh[0], bh[1]);
                mma_bf16(oacc[2 * g + 1], aph, bh[2], bh[3]);
                mma_bf16(oacc[2 * g + 1], aph, bl[2], bl[3]);
                mma_bf16(oacc[2 * g + 1], apl, bh[2], bh[3]);
            }
        }
    }

    // ---- normalize + write ----
    const float i0 = 1.0f / lrun0;
    const float i1 = 1.0f / lrun1;
    const size_t rowg = (size_t)(b * Tt + t0 + w * 16 + (lane >> 2));
#pragma unroll
    for (int nt = 0; nt < 16; nt++) {
        int col = h * HD + nt * 8 + 2 * (lane & 3);
        *(float2*)&g_Y[rowg * Cc + col] = make_float2(oacc[nt][0] * i0, oacc[nt][1] * i0);
        *(float2*)&g_Y[(rowg + 8) * Cc + col] = make_float2(oacc[nt][2] * i1, oacc[nt][3] * i1);
    }
}

// ---------------------------------------------------------------------------
// Launch
// ---------------------------------------------------------------------------
extern "C" void kernel_launch(void* const* d_in, const int* in_sizes, int n_in,
                              void* d_out, int out_size)
{
    const float* x  = (const float*)d_in[0];
    const float* Wq = (const float*)d_in[1];
    const float* Wk = (const float*)d_in[2];
    const float* Wv = (const float*)d_in[3];
    const float* Wo = (const float*)d_in[4];
    float* out = (float*)d_out;

    void *pQ, *pK, *pV, *pY;
    cudaGetSymbolAddress(&pQ, g_Q);
    cudaGetSymbolAddress(&pK, g_K);
    cudaGetSymbolAddress(&pV, g_V);
    cudaGetSymbolAddress(&pY, g_Y);

    const int M = Bb * Tt;

    tf32gemm<<<dim3(Cc / 128, M / 128), 256>>>(x, Wq, (float*)pQ, M, Cc, Cc);
    tf32gemm<<<dim3((NKV * HD) / 128, M / 128), 256>>>(x, Wk, (float*)pK, M, NKV * HD, Cc);
    tf32gemm<<<dim3((NKV * HD) / 128, M / 128), 256>>>(x, Wv, (float*)pV, M, NKV * HD, Cc);

    cudaFuncSetAttribute(attn_mma, cudaFuncAttributeMaxDynamicSharedMemorySize,
                         ATTN_SMEM_BYTES);
    attn_mma<<<dim3(Tt / 128, NH, Bb), 256, ATTN_SMEM_BYTES>>>();

    tf32gemm<<<dim3(Cc / 128, M / 128), 256>>>((const float*)pY, Wo, out, M, Cc, Cc);
}